// round 9
// baseline (speedup 1.0000x reference)
#include <cuda_runtime.h>
#include <cstdint>
#include <cmath>

#define BB 512
#define NN 1000
#define CC 50
#define CCP 51              // pitch for transposed cluster tile (odd -> conflict-free)
#define EE 128
#define HH 8
#define DD 16
#define NEGV (-1e9f)

// scratch (no cudaMalloc allowed)
__device__ float g_Wqf [3*EE*EE];         // Wq @ mha_Wq   (384 x 128), [i][j]
__device__ float g_WkfT[EE*EE];           // (Wk @ mha_Wk)^T : [j][e]
__device__ float g_Wvf [EE*EE];           // Wv @ mha_Wv    : [e][j]
__device__ float g_WksT[EE*EE];           // Wks^T          : [f][e]

// ---------------------------------------------------------------------------
// Kernel 0: weight prep (batch-independent). grid 768, 128 threads.
// ---------------------------------------------------------------------------
__global__ void __launch_bounds__(128) k_fuse(
    const float* __restrict__ Wq, const float* __restrict__ Wk,
    const float* __restrict__ Wv, const float* __restrict__ Wks,
    const float* __restrict__ mWq, const float* __restrict__ mWk,
    const float* __restrict__ mWv)
{
    const int r = blockIdx.x, t = threadIdx.x;
    if (r < 3*EE) {
        const float* a_ = Wq + r*EE;
        float s0=0.f,s1=0.f,s2=0.f,s3=0.f;
        #pragma unroll 8
        for (int e = 0; e < EE; e += 4) {
            s0 += a_[e  ] * mWq[(e  )*EE + t];
            s1 += a_[e+1] * mWq[(e+1)*EE + t];
            s2 += a_[e+2] * mWq[(e+2)*EE + t];
            s3 += a_[e+3] * mWq[(e+3)*EE + t];
        }
        g_Wqf[r*EE + t] = (s0+s1)+(s2+s3);
    } else if (r < 4*EE) {
        const int e0 = r - 3*EE;
        const float* a_ = Wk + e0*EE;
        float s0=0.f,s1=0.f,s2=0.f,s3=0.f;
        #pragma unroll 8
        for (int x = 0; x < EE; x += 4) {
            s0 += a_[x  ] * mWk[(x  )*EE + t];
            s1 += a_[x+1] * mWk[(x+1)*EE + t];
            s2 += a_[x+2] * mWk[(x+2)*EE + t];
            s3 += a_[x+3] * mWk[(x+3)*EE + t];
        }
        g_WkfT[t*EE + e0] = (s0+s1)+(s2+s3);   // store transposed
    } else if (r < 5*EE) {
        const int e0 = r - 4*EE;
        const float* a_ = Wv + e0*EE;
        float s0=0.f,s1=0.f,s2=0.f,s3=0.f;
        #pragma unroll 8
        for (int x = 0; x < EE; x += 4) {
            s0 += a_[x  ] * mWv[(x  )*EE + t];
            s1 += a_[x+1] * mWv[(x+1)*EE + t];
            s2 += a_[x+2] * mWv[(x+2)*EE + t];
            s3 += a_[x+3] * mWv[(x+3)*EE + t];
        }
        g_Wvf[e0*EE + t] = (s0+s1)+(s2+s3);
    } else {
        const int f = r - 5*EE;
        g_WksT[f*EE + t] = Wks[t*EE + f];      // transpose
    }
}

// ---------------------------------------------------------------------------
// Kernel 1: EVERYTHING per batch in one block. grid 512, 256 threads.
// Node reduction fused in front of the math chain so all blocks' DRAM
// streaming overlaps all blocks' compute chains (single resident wave:
// launch_bounds(256,4), smem ~53.5KB -> 4 blocks/SM, 592 slots >= 512).
// ---------------------------------------------------------------------------
__global__ void __launch_bounds__(256, 4) k_all(
    const float* __restrict__ nodes,
    const int* __restrict__ mask, const int* __restrict__ cmask,
    const float* __restrict__ depot, const float* __restrict__ CE,
    const float* __restrict__ cur,   const float* __restrict__ augc,
    const float* __restrict__ gein,  const float* __restrict__ Wo,
    const int* __restrict__ isnew, const int* __restrict__ vcm_g,
    const int* __restrict__ guid_in, float* __restrict__ out)
{
    const int b = blockIdx.x, t = threadIdx.x;
    const int t2 = t & 127, half = t >> 7;
    const int warp = t >> 5, lane = t & 31;

    __shared__ float   sCET[EE*CCP];    // transposed cluster embeddings
    __shared__ uint8_t sM[NN], sC[NN];
    __shared__ float4  sR0[8][32], sR1[8][32];
    __shared__ float   sCtx[3*EE];
    __shared__ float   sUC[EE];
    __shared__ float   sP2[2][EE];
    __shared__ float   sQ[EE];
    __shared__ float   sKQ[HH*EE];
    __shared__ float   sSc[HH*CC];
    __shared__ float   sAt[HH*CC];
    __shared__ float   sAce[HH*EE];
    __shared__ float   sGl[EE];
    __shared__ float   sOut[EE];
    __shared__ float   sW2[EE];
    __shared__ float   sLgP[4][CC];
    __shared__ float   sLg[CC];
    __shared__ int     sVcm[CC];
    __shared__ float   sMax, sLse;
    __shared__ int     sArg;

    // ---- cluster tile (transposed) + masks into smem ----
    {
        const float* src = CE + (size_t)b*CC*EE;
        #pragma unroll
        for (int cc = 0; cc < 25; cc++) {
            int c = half*25 + cc;
            sCET[t2*CCP + c] = src[c*EE + t2];
        }
        const int* m  = mask  + b*NN;
        const int* cm = cmask + b*NN;
        for (int i = t; i < NN; i += 256) {
            sM[i] = (uint8_t)(m[i]  != 0);
            sC[i] = (uint8_t)(cm[i] != 0);
        }
        if (t < CC) sVcm[t] = (vcm_g[b*CC + t] != 0);
    }
    __syncthreads();

    // ---- masked node reduction: warp w owns rows w, w+8, ... ----
    {
        const float4* base = (const float4*)(nodes + (size_t)b*NN*EE);
        float4 a0 = make_float4(0.f,0.f,0.f,0.f);
        float4 a1 = make_float4(0.f,0.f,0.f,0.f);
        for (int r = warp; r < NN; r += 8) {
            if (!sM[r]) {                    // warp-uniform: skip masked rows
                float4 v = __ldg(base + r*32 + lane);
                a0.x += v.x; a0.y += v.y; a0.z += v.z; a0.w += v.w;
                if (!sC[r]) { a1.x += v.x; a1.y += v.y; a1.z += v.z; a1.w += v.w; }
            }
        }
        sR0[warp][lane] = a0;
        sR1[warp][lane] = a1;
    }
    __syncthreads();

    // ---- combine partials + assemble context ----
    if (t < 128) {
        const float* p0 = (const float*)sR0;
        const float* p1 = (const float*)sR1;
        float s0 = 0.f, s1 = 0.f;
        #pragma unroll
        for (int w = 0; w < 8; w++) { s0 += p0[w*128 + t]; s1 += p1[w*128 + t]; }
        sCtx[t]        = s0 * (1.f/NN);
        sUC[t]         = s1 * (1.f/NN);
        sCtx[EE + t]   = cur[b*EE + t];
        sCtx[2*EE + t] = depot[b*EE + t];
    }
    __syncthreads();

    if (t == 0) {                      // vcm[0] = !all(vcm[1:])
        int all = 1;
        for (int c = 1; c < CC; c++) all &= (sVcm[c] != 0);
        sVcm[0] = !all;
    }

    // ---- q projection, split-K over halves (192 MACs each, 4 accs) ----
    {
        const int i0 = half*192;
        float a0=0.f,a1=0.f,a2=0.f,a3=0.f;
        #pragma unroll 4
        for (int i = 0; i < 192; i += 4) {
            a0 += sCtx[i0+i  ] * g_Wqf[(i0+i  )*EE + t2];
            a1 += sCtx[i0+i+1] * g_Wqf[(i0+i+1)*EE + t2];
            a2 += sCtx[i0+i+2] * g_Wqf[(i0+i+2)*EE + t2];
            a3 += sCtx[i0+i+3] * g_Wqf[(i0+i+3)*EE + t2];
        }
        sP2[half][t2] = (a0+a1)+(a2+a3);
    }
    __syncthreads();
    if (half == 0) sQ[t2] = sP2[0][t2] + sP2[1][t2];
    __syncthreads();

    // ---- kq[h][e]: 1024 outputs over 256 threads (4 each), 16 MACs ----
    #pragma unroll
    for (int k = 0; k < 4; k++) {
        int idx = t + 256*k;
        int h = idx >> 7, e = idx & 127;
        float a0=0.f,a1=0.f;
        #pragma unroll
        for (int d = 0; d < DD; d += 2) {
            a0 += sQ[h*DD + d  ] * g_WkfT[(h*DD + d  )*EE + e];
            a1 += sQ[h*DD + d+1] * g_WkfT[(h*DD + d+1)*EE + e];
        }
        sKQ[h*EE + e] = a0 + a1;
    }
    __syncthreads();

    // ---- scores: warp = head; lanes own c=lane, c=lane+32; kq broadcast ----
    {
        const int h = warp;
        const int c0 = lane;
        const int c1 = (lane + 32 < CC) ? lane + 32 : CC - 1;  // clamped
        float a00=0.f,a01=0.f,a10=0.f,a11=0.f;
        #pragma unroll 4
        for (int e = 0; e < EE; e += 2) {
            float k0 = sKQ[h*EE + e];       // broadcast
            float k1 = sKQ[h*EE + e + 1];
            a00 += sCET[(e  )*CCP + c0] * k0;
            a01 += sCET[(e+1)*CCP + c0] * k1;
            a10 += sCET[(e  )*CCP + c1] * k0;
            a11 += sCET[(e+1)*CCP + c1] * k1;
        }
        float s0 = (a00 + a01) * 0.25f;
        float s1 = (a10 + a11) * 0.25f;
        if (sVcm[c0]) s0 = NEGV;
        sSc[h*CC + c0] = s0;
        if (lane + 32 < CC) {
            if (sVcm[c1]) s1 = NEGV;
            sSc[h*CC + c1] = s1;
        }
    }
    __syncthreads();

    // ---- softmax: warp h owns head h ----
    {
        int h = warp;
        float v0 = sSc[h*CC + lane];
        float v1 = (lane < CC-32) ? sSc[h*CC + lane + 32] : -3e38f;
        float mx = fmaxf(v0, v1);
        #pragma unroll
        for (int o = 16; o > 0; o >>= 1)
            mx = fmaxf(mx, __shfl_xor_sync(0xffffffffu, mx, o));
        float e0 = expf(v0 - mx);
        float e1 = (lane < CC-32) ? expf(v1 - mx) : 0.f;
        float sm = e0 + e1;
        #pragma unroll
        for (int o = 16; o > 0; o >>= 1)
            sm += __shfl_xor_sync(0xffffffffu, sm, o);
        float inv = 1.f / sm;
        sAt[h*CC + lane] = e0 * inv;
        if (lane < CC-32) sAt[h*CC + lane + 32] = e1 * inv;
    }
    __syncthreads();

    // ---- a_ce: warp = head; thread owns 4 strided e; attn broadcast ----
    {
        const int h = warp;
        float a0=0.f,a1=0.f,a2=0.f,a3=0.f;
        #pragma unroll 2
        for (int c = 0; c < CC; c++) {
            float at = sAt[h*CC + c];       // broadcast
            a0 += at * sCET[(lane      )*CCP + c];
            a1 += at * sCET[(lane +  32)*CCP + c];
            a2 += at * sCET[(lane +  64)*CCP + c];
            a3 += at * sCET[(lane +  96)*CCP + c];
        }
        sAce[h*EE + lane      ] = a0;
        sAce[h*EE + lane +  32] = a1;
        sAce[h*EE + lane +  64] = a2;
        sAce[h*EE + lane +  96] = a3;
    }
    __syncthreads();

    // ---- glimpse[j=t2]: 128-MAC split-K over halves (h = j/16) ----
    {
        int h = t2 / DD;
        const int e0 = half*64;
        float a0=0.f,a1=0.f,a2=0.f,a3=0.f;
        #pragma unroll 4
        for (int e = 0; e < 64; e += 4) {
            a0 += sAce[h*EE + e0+e  ] * g_Wvf[(e0+e  )*EE + t2];
            a1 += sAce[h*EE + e0+e+1] * g_Wvf[(e0+e+1)*EE + t2];
            a2 += sAce[h*EE + e0+e+2] * g_Wvf[(e0+e+2)*EE + t2];
            a3 += sAce[h*EE + e0+e+3] * g_Wvf[(e0+e+3)*EE + t2];
        }
        sP2[half][t2] = (a0+a1)+(a2+a3);
    }
    __syncthreads();
    if (half == 0) sGl[t2] = sP2[0][t2] + sP2[1][t2];
    __syncthreads();

    // ---- out = glimpse @ Wo: split-K over halves ----
    {
        const int j0 = half*64;
        float a0=0.f,a1=0.f,a2=0.f,a3=0.f;
        #pragma unroll 4
        for (int j = 0; j < 64; j += 4) {
            a0 += sGl[j0+j  ] * Wo[(j0+j  )*EE + t2];
            a1 += sGl[j0+j+1] * Wo[(j0+j+1)*EE + t2];
            a2 += sGl[j0+j+2] * Wo[(j0+j+2)*EE + t2];
            a3 += sGl[j0+j+3] * Wo[(j0+j+3)*EE + t2];
        }
        sP2[half][t2] = (a0+a1)+(a2+a3);
    }
    __syncthreads();
    if (half == 0) sOut[t2] = sP2[0][t2] + sP2[1][t2];
    __syncthreads();

    // ---- w2[e=t2]: split-K over halves ----
    {
        const int f0 = half*64;
        float a0=0.f,a1=0.f,a2=0.f,a3=0.f;
        #pragma unroll 4
        for (int f = 0; f < 64; f += 4) {
            a0 += g_WksT[(f0+f  )*EE + t2] * sOut[f0+f  ];
            a1 += g_WksT[(f0+f+1)*EE + t2] * sOut[f0+f+1];
            a2 += g_WksT[(f0+f+2)*EE + t2] * sOut[f0+f+2];
            a3 += g_WksT[(f0+f+3)*EE + t2] * sOut[f0+f+3];
        }
        sP2[half][t2] = (a0+a1)+(a2+a3);
    }
    __syncthreads();
    if (half == 0) sW2[t2] = sP2[0][t2] + sP2[1][t2];
    __syncthreads();

    // ---- logit[c]: 50 outputs, split over 4 quarters of e ----
    {
        int c = t & 63, q4 = t >> 6;
        if (c < CC) {
            const int e0 = q4*32;
            float a0=0.f,a1=0.f;
            #pragma unroll 4
            for (int e = 0; e < 32; e += 2) {
                a0 += sCET[(e0+e  )*CCP + c] * sW2[e0+e  ];
                a1 += sCET[(e0+e+1)*CCP + c] * sW2[e0+e+1];
            }
            sLgP[q4][c] = a0 + a1;
        }
    }
    __syncthreads();
    if (t < CC) {
        float a = (sLgP[0][t] + sLgP[1][t]) + (sLgP[2][t] + sLgP[3][t]);
        a *= 0.08838834764831845f;     // 1/sqrt(128)
        a = tanhf(a) * 10.f;
        if (sVcm[t]) a = NEGV;
        sLg[t] = a;
    }
    __syncthreads();

    // ---- argmax (first-index ties) + logsumexp, warp 0 via shfl ----
    if (warp == 0) {
        float v0 = sLg[lane];
        float v1 = (lane < CC-32) ? sLg[lane + 32] : -3e38f;
        float v = v0; int ix = lane;
        if (v1 > v) { v = v1; ix = lane + 32; }
        #pragma unroll
        for (int o = 16; o > 0; o >>= 1) {
            float ov = __shfl_xor_sync(0xffffffffu, v, o);
            int   oi = __shfl_xor_sync(0xffffffffu, ix, o);
            if (ov > v || (ov == v && oi < ix)) { v = ov; ix = oi; }
        }
        float mx = v;
        float sm = expf(v0 - mx) + ((lane < CC-32) ? expf(v1 - mx) : 0.f);
        #pragma unroll
        for (int o = 16; o > 0; o >>= 1)
            sm += __shfl_xor_sync(0xffffffffu, sm, o);
        if (lane == 0) { sMax = mx; sLse = logf(sm); sArg = ix; }
    }
    __syncthreads();

    const int  guid = sArg;
    const bool isn  = isnew[b] != 0;
    const float ge  = sCET[t2*CCP + guid];

    const size_t OFF1 = (size_t)BB*4*EE;            // guid_embed_out
    const size_t OFF2 = OFF1 + (size_t)BB*EE;       // guid_out
    const size_t OFF3 = OFF2 + BB;                  // clu_prob

    float* ao = out + (size_t)b*4*EE;
    const float* ac = augc + (size_t)b*4*EE;
    if (half == 0) {
        ao[t2]        = isn ? sUC[t2]          : ac[t2];
        ao[2*EE + t2] = isn ? ge               : ac[2*EE + t2];
        out[OFF1 + (size_t)b*EE + t2] = isn ? ge : gein[b*EE + t2];
    } else {
        ao[EE + t2]   = isn ? sCtx[EE + t2]    : ac[EE + t2];
        ao[3*EE + t2] = isn ? sCtx[2*EE + t2]  : ac[3*EE + t2];
    }
    if (t == 0) out[OFF2 + b] = (float)(isn ? guid : guid_in[b]);
    if (t < CC) out[OFF3 + (size_t)b*CC + t] = isn ? (sLg[t] - sMax - sLse) : 0.f;
}

// ---------------------------------------------------------------------------
extern "C" void kernel_launch(void* const* d_in, const int* in_sizes, int n_in,
                              void* d_out, int out_size) {
    const float* depot = (const float*)d_in[0];
    const float* CE    = (const float*)d_in[1];
    const float* cur   = (const float*)d_in[2];
    const float* nodes = (const float*)d_in[3];
    const float* augc  = (const float*)d_in[4];
    const float* gein  = (const float*)d_in[5];
    const float* Wq    = (const float*)d_in[6];
    const float* Wk    = (const float*)d_in[7];
    const float* Wv    = (const float*)d_in[8];
    const float* Wks   = (const float*)d_in[9];
    const float* mWq   = (const float*)d_in[10];
    const float* mWk   = (const float*)d_in[11];
    const float* mWv   = (const float*)d_in[12];
    const float* Wo    = (const float*)d_in[13];
    const int* isnew   = (const int*)d_in[14];   // bool -> int32
    const int* mask    = (const int*)d_in[15];   // bool -> int32
    const int* cmask   = (const int*)d_in[16];   // bool -> int32
    const int* vcm     = (const int*)d_in[17];   // bool -> int32
    const int* guid    = (const int*)d_in[18];
    // d_in[19] = step (unused)

    k_fuse<<<6*EE, 128>>>(Wq, Wk, Wv, Wks, mWq, mWk, mWv);
    k_all<<<BB, 256>>>(nodes, mask, cmask, depot, CE, cur, augc, gein, Wo,
                       isnew, vcm, guid, (float*)d_out);
}